// round 1
// baseline (speedup 1.0000x reference)
#include <cuda_runtime.h>
#include <math.h>

// ---------------- problem constants ----------------
#define BATCH    2
#define SEQLEN   4096
#define NTOK     8192            // BATCH*SEQLEN
#define DMODEL   1024
#define DINNER   2048
#define DSTATE   64
#define NHEADS   32
#define HDIM     64
#define CONVK    4
#define CHUNKSZ  128
#define NCHUNK   32              // SEQLEN/CHUNK
#define DXBC     6144            // DINNER + 2*NHEADS*DSTATE
#define DPROJ    8224            // DXBC + DINNER + NHEADS

// ---------------- device scratch (allocation-free) ----------------
__device__ float g_proj[(size_t)NTOK * DPROJ];            // 269 MB
__device__ float g_xbc[(size_t)NTOK * DXBC];              // 201 MB (post conv+silu)
__device__ float g_dacum[BATCH * NHEADS * NCHUNK * CHUNKSZ];
__device__ float g_states[(size_t)BATCH * NCHUNK * NHEADS * HDIM * DSTATE];
__device__ float g_prev[(size_t)BATCH * NCHUNK * NHEADS * HDIM * DSTATE];
__device__ float g_yz[(size_t)NTOK * DINNER];             // y * silu(z)

// ============================================================
// Tiled fp32 GEMM (NT): C[m,n] = sum_k A[m,k] * B[n,k]
// A: [M,K] row-major, B: [N,K] row-major. M%128==0, K%16==0. N guarded.
// ============================================================
__global__ void __launch_bounds__(256) gemm_nt(const float* __restrict__ A,
                                               const float* __restrict__ B,
                                               float* __restrict__ C,
                                               int M, int N, int K)
{
    __shared__ float As[16][132];
    __shared__ float Bs[16][132];
    const int bm = blockIdx.y * 128;
    const int bn = blockIdx.x * 128;
    const int tid = threadIdx.x;
    const int tr = tid >> 4;      // 0..15
    const int tc = tid & 15;      // 0..15

    float acc[8][8];
#pragma unroll
    for (int i = 0; i < 8; i++)
#pragma unroll
        for (int j = 0; j < 8; j++) acc[i][j] = 0.f;

    for (int k0 = 0; k0 < K; k0 += 16) {
#pragma unroll
        for (int jj = 0; jj < 2; jj++) {
            int flat = tid + jj * 256;
            int r = flat >> 2;                 // 0..127
            int c4 = (flat & 3) << 2;          // 0,4,8,12
            float4 va = *(const float4*)(A + (size_t)(bm + r) * K + k0 + c4);
            As[c4 + 0][r] = va.x; As[c4 + 1][r] = va.y;
            As[c4 + 2][r] = va.z; As[c4 + 3][r] = va.w;
            int gn = bn + r;
            float4 vb = make_float4(0.f, 0.f, 0.f, 0.f);
            if (gn < N) vb = *(const float4*)(B + (size_t)gn * K + k0 + c4);
            Bs[c4 + 0][r] = vb.x; Bs[c4 + 1][r] = vb.y;
            Bs[c4 + 2][r] = vb.z; Bs[c4 + 3][r] = vb.w;
        }
        __syncthreads();
#pragma unroll
        for (int kk = 0; kk < 16; kk++) {
            float4 a0 = *(const float4*)&As[kk][tr * 8];
            float4 a1 = *(const float4*)&As[kk][tr * 8 + 4];
            float4 b0 = *(const float4*)&Bs[kk][tc * 8];
            float4 b1 = *(const float4*)&Bs[kk][tc * 8 + 4];
            float a[8] = {a0.x, a0.y, a0.z, a0.w, a1.x, a1.y, a1.z, a1.w};
            float b[8] = {b0.x, b0.y, b0.z, b0.w, b1.x, b1.y, b1.z, b1.w};
#pragma unroll
            for (int i = 0; i < 8; i++)
#pragma unroll
                for (int j = 0; j < 8; j++)
                    acc[i][j] = fmaf(a[i], b[j], acc[i][j]);
        }
        __syncthreads();
    }

#pragma unroll
    for (int i = 0; i < 8; i++) {
        int gm = bm + tr * 8 + i;
#pragma unroll
        for (int j = 0; j < 8; j++) {
            int gn = bn + tc * 8 + j;
            if (gn < N) C[(size_t)gm * N + gn] = acc[i][j];
        }
    }
}

// ============================================================
// Depthwise causal conv (K=4) + bias + SiLU over xBC channels
// ============================================================
__global__ void conv_silu_kernel(const float* __restrict__ cw,
                                 const float* __restrict__ cb)
{
    long gi = (long)blockIdx.x * blockDim.x + threadIdx.x;
    if (gi >= (long)NTOK * DXBC) return;
    int ch = (int)(gi % DXBC);
    int t  = (int)(gi / DXBC);
    int l  = t & (SEQLEN - 1);
    int b  = t >> 12;

    float acc = cb[ch];
#pragma unroll
    for (int j = 0; j < CONVK; j++) {
        int ls = l - 3 + j;
        if (ls >= 0)
            acc = fmaf(g_proj[(size_t)(b * SEQLEN + ls) * DPROJ + ch],
                       cw[ch * CONVK + j], acc);
    }
    float s = acc / (1.f + expf(-acc));       // silu
    g_xbc[(size_t)t * DXBC + ch] = s;
}

// ============================================================
// dA = -softplus(A_log); per-chunk inclusive cumsum
// g_dacum layout: [b][h][c][s]
// ============================================================
__global__ void dacum_kernel()
{
    int gi = blockIdx.x * blockDim.x + threadIdx.x;
    if (gi >= BATCH * NHEADS * NCHUNK) return;
    int c = gi & 31;
    int h = (gi >> 5) & 31;
    int b = gi >> 10;
    int t0 = b * SEQLEN + c * CHUNKSZ;
    float acc = 0.f;
    for (int s = 0; s < CHUNKSZ; s++) {
        float v = g_proj[(size_t)(t0 + s) * DPROJ + (DXBC + DINNER) + h];
        // stable softplus = max(v,0) + log1p(exp(-|v|))
        float sp = fmaxf(v, 0.f) + log1pf(expf(-fabsf(v)));
        acc -= sp;
        g_dacum[gi * CHUNKSZ + s] = acc;
    }
}

// ============================================================
// Per-(b,c,h) chunk states: states[p,n] = sum_s B[s,n]*exp(da[127]-da[s])*x[s,p]
// g_states layout: [b][c][h][p][n]
// ============================================================
#define SMEM_STATES ((2 * 128 * 65 + 128) * 4)
__global__ void __launch_bounds__(256, 1) states_kernel()
{
    extern __shared__ float sm[];
    float* Bs = sm;                 // [128][65]
    float* xs = sm + 128 * 65;      // [128][65]
    float* da = xs + 128 * 65;      // [128]

    int bi = blockIdx.x;
    int h = bi & 31, c = (bi >> 5) & 31, b = bi >> 10;
    int tid = threadIdx.x;
    int base_t = b * SEQLEN + c * CHUNKSZ;
    int dab = ((b * 32 + h) * 32 + c) * CHUNKSZ;

    if (tid < 128) da[tid] = g_dacum[dab + tid];
    __syncthreads();
    float da_last = da[127];

#pragma unroll
    for (int i = 0; i < 32; i++) {
        int flat = tid + 256 * i;
        int s = flat >> 6, p = flat & 63;
        size_t goff = (size_t)(base_t + s) * DXBC + h * 64 + p;
        float dec = __expf(da_last - da[s]);
        xs[s * 65 + p] = g_xbc[goff] * dec;              // x (cols 0..2047)
        Bs[s * 65 + p] = g_xbc[goff + DINNER];           // B (cols 2048..4095)
    }
    __syncthreads();

    int n = tid & 63, pg = tid >> 6;
    float acc[16];
#pragma unroll
    for (int i = 0; i < 16; i++) acc[i] = 0.f;
    for (int s = 0; s < CHUNKSZ; s++) {
        float bv = Bs[s * 65 + n];
#pragma unroll
        for (int i = 0; i < 16; i++)
            acc[i] = fmaf(bv, xs[s * 65 + pg + 4 * i], acc[i]);
    }
    size_t sb = (size_t)((b * 32 + c) * 32 + h) * (HDIM * DSTATE);
#pragma unroll
    for (int i = 0; i < 16; i++)
        g_states[sb + (pg + 4 * i) * 64 + n] = acc[i];
}

// ============================================================
// Inter-chunk scan: prev[c] = prev[c-1]*dec[c-1] + states[c-1], prev[0]=0
// One block per (b,h); 256 threads x 16 elems cover 64*64.
// ============================================================
__global__ void __launch_bounds__(256, 1) scan_kernel()
{
    int bi = blockIdx.x;
    int b = bi >> 5, h = bi & 31;
    int tid = threadIdx.x;
    float carry[16];
#pragma unroll
    for (int i = 0; i < 16; i++) carry[i] = 0.f;
    for (int c = 0; c < NCHUNK; c++) {
        size_t sb = (size_t)((b * 32 + c) * 32 + h) * (HDIM * DSTATE);
        float dec = expf(g_dacum[((b * 32 + h) * 32 + c) * CHUNKSZ + 127]);
#pragma unroll
        for (int i = 0; i < 16; i++) {
            int idx = tid + 256 * i;
            g_prev[sb + idx] = carry[i];
            carry[i] = fmaf(carry[i], dec, g_states[sb + idx]);
        }
    }
}

// ============================================================
// Fused Y kernel per (b,c,h):
//   G[l,s] = (s<=l) ? (C_l . B_s) * exp(da[l]-da[s]) : 0
//   Y[l,p] = sum_s G[l,s] x[s,p] + exp(da[l]) * sum_n C[l,n] prev[p,n] + D[h]*x[l,p]
//   yz[t,ch] = Y * silu(z[t,ch] + z_bias[ch])
// ============================================================
#define SMEM_Y ((3 * 128 * 65 + 128 * 129 + 64 * 65 + 128) * 4)
__global__ void __launch_bounds__(256, 1) y_kernel(const float* __restrict__ zb,
                                                   const float* __restrict__ Dp)
{
    extern __shared__ float sm[];
    float* Cs  = sm;                          // [128][65]
    float* Bs  = Cs + 128 * 65;               // [128][65]
    float* xs  = Bs + 128 * 65;               // [128][65]
    float* G   = xs + 128 * 65;               // [128][129]
    float* pT  = G + 128 * 129;               // [64][65]  prev transposed [n][p]
    float* da  = pT + 64 * 65;                // [128]

    int bi = blockIdx.x;
    int h = bi & 31, c = (bi >> 5) & 31, b = bi >> 10;
    int tid = threadIdx.x;
    int base_t = b * SEQLEN + c * CHUNKSZ;
    int dab = ((b * 32 + h) * 32 + c) * CHUNKSZ;
    size_t pb = (size_t)((b * 32 + c) * 32 + h) * (HDIM * DSTATE);

    if (tid < 128) da[tid] = g_dacum[dab + tid];
#pragma unroll
    for (int i = 0; i < 32; i++) {
        int flat = tid + 256 * i;
        int s = flat >> 6, p = flat & 63;
        size_t goff = (size_t)(base_t + s) * DXBC + h * 64 + p;
        xs[s * 65 + p] = g_xbc[goff];                     // raw x
        Bs[s * 65 + p] = g_xbc[goff + DINNER];            // B
        Cs[s * 65 + p] = g_xbc[goff + 2 * DINNER];        // C
    }
#pragma unroll
    for (int i = 0; i < 16; i++) {
        int flat = tid + 256 * i;                          // p*64+n order
        int p = flat >> 6, n = flat & 63;
        pT[n * 65 + p] = g_prev[pb + flat];
    }
    __syncthreads();

    // ---- phase 1: G = (C B^T) .* L  (strided 8x8 tiles, conflict-free) ----
    {
        int tr = tid >> 4, tc = tid & 15;
        float accg[8][8];
#pragma unroll
        for (int i = 0; i < 8; i++)
#pragma unroll
            for (int j = 0; j < 8; j++) accg[i][j] = 0.f;
        for (int n = 0; n < DSTATE; n++) {
            float a[8], bb[8];
#pragma unroll
            for (int i = 0; i < 8; i++) a[i] = Cs[(tr + 16 * i) * 65 + n];
#pragma unroll
            for (int j = 0; j < 8; j++) bb[j] = Bs[(tc + 16 * j) * 65 + n];
#pragma unroll
            for (int i = 0; i < 8; i++)
#pragma unroll
                for (int j = 0; j < 8; j++)
                    accg[i][j] = fmaf(a[i], bb[j], accg[i][j]);
        }
#pragma unroll
        for (int i = 0; i < 8; i++) {
            int l = tr + 16 * i;
            float dal = da[l];
#pragma unroll
            for (int j = 0; j < 8; j++) {
                int s = tc + 16 * j;
                G[l * 129 + s] = (s <= l) ? accg[i][j] * __expf(dal - da[s]) : 0.f;
            }
        }
    }
    __syncthreads();

    // ---- phase 2: Y = G@x + exp(da[l])*(C . prev) + D*x; write yz ----
    {
        int p = tid & 63;
        int tr2 = tid >> 6;                   // 0..3 ; l = tr2 + 4*i
        float acc[32], acc2[32];
#pragma unroll
        for (int i = 0; i < 32; i++) { acc[i] = 0.f; acc2[i] = 0.f; }

        for (int s = 0; s < CHUNKSZ; s++) {
            float xv = xs[s * 65 + p];
#pragma unroll
            for (int i = 0; i < 32; i++)
                acc[i] = fmaf(G[(tr2 + 4 * i) * 129 + s], xv, acc[i]);
        }
        for (int n = 0; n < DSTATE; n++) {
            float pv = pT[n * 65 + p];
#pragma unroll
            for (int i = 0; i < 32; i++)
                acc2[i] = fmaf(Cs[(tr2 + 4 * i) * 65 + n], pv, acc2[i]);
        }

        float Dh = Dp[h];
        int chn = h * 64 + p;
        float zbias = zb[chn];
#pragma unroll
        for (int i = 0; i < 32; i++) {
            int l = tr2 + 4 * i;
            int t = base_t + l;
            float yv = acc[i] + __expf(da[l]) * acc2[i] + Dh * xs[l * 65 + p];
            float zv = g_proj[(size_t)t * DPROJ + DXBC + chn] + zbias;
            float sil = zv / (1.f + expf(-zv));
            g_yz[(size_t)t * DINNER + chn] = yv * sil;
        }
    }
}

// ============================================================
// launch
// ============================================================
extern "C" void kernel_launch(void* const* d_in, const int* in_sizes, int n_in,
                              void* d_out, int out_size)
{
    const float* u          = (const float*)d_in[0];
    const float* in_proj_w  = (const float*)d_in[1];
    const float* z_bias     = (const float*)d_in[2];
    const float* conv_w     = (const float*)d_in[3];
    const float* conv_b     = (const float*)d_in[4];
    const float* Dparam     = (const float*)d_in[5];
    const float* out_proj_w = (const float*)d_in[6];
    float* out = (float*)d_out;

    void *p_proj = nullptr, *p_yz = nullptr;
    cudaGetSymbolAddress(&p_proj, g_proj);
    cudaGetSymbolAddress(&p_yz, g_yz);

    cudaFuncSetAttribute(states_kernel, cudaFuncAttributeMaxDynamicSharedMemorySize, SMEM_STATES);
    cudaFuncSetAttribute(y_kernel, cudaFuncAttributeMaxDynamicSharedMemorySize, SMEM_Y);

    // 1) in_proj GEMM: [8192,1024] x [8224,1024]^T -> g_proj
    {
        dim3 grid((DPROJ + 127) / 128, NTOK / 128);
        gemm_nt<<<grid, 256>>>(u, in_proj_w, (float*)p_proj, NTOK, DPROJ, DMODEL);
    }
    // 2) conv + silu
    {
        long tot = (long)NTOK * DXBC;
        conv_silu_kernel<<<(unsigned)((tot + 255) / 256), 256>>>(conv_w, conv_b);
    }
    // 3) dA cumsum
    dacum_kernel<<<(BATCH * NHEADS * NCHUNK + 255) / 256, 256>>>();
    // 4) chunk states
    states_kernel<<<BATCH * NCHUNK * NHEADS, 256, SMEM_STATES>>>();
    // 5) inter-chunk scan
    scan_kernel<<<BATCH * NHEADS, 256>>>();
    // 6) fused Y + gating
    y_kernel<<<BATCH * NCHUNK * NHEADS, 256, SMEM_Y>>>(z_bias, Dparam);
    // 7) out_proj GEMM: [8192,2048] x [1024,2048]^T -> out
    {
        dim3 grid(DMODEL / 128, NTOK / 128);
        gemm_nt<<<grid, 256>>>((const float*)p_yz, out_proj_w, out, NTOK, DMODEL, DINNER);
    }
}

// round 3
// speedup vs baseline: 2.2823x; 2.2823x over previous
#include <cuda_runtime.h>
#include <cstdint>
#include <math.h>

// ---------------- problem constants ----------------
#define BATCH    2
#define SEQLEN   4096
#define NTOK     8192
#define DMODEL   1024
#define DINNER   2048
#define DSTATE   64
#define NHEADS   32
#define HDIM     64
#define CONVK    4
#define CHUNKSZ  128
#define NCHUNK   32
#define DXBC     6144
#define DPROJ    8224

// ---------------- device scratch (allocation-free) ----------------
__device__ float g_proj[(size_t)NTOK * DPROJ];
__device__ float g_xbc[(size_t)NTOK * DXBC];
__device__ float g_dacum[BATCH * NHEADS * NCHUNK * CHUNKSZ];
__device__ float g_states[(size_t)BATCH * NCHUNK * NHEADS * HDIM * DSTATE];
__device__ float g_prev[(size_t)BATCH * NCHUNK * NHEADS * HDIM * DSTATE];
__device__ float g_yz[(size_t)NTOK * DINNER];
__device__ float g_ua[(size_t)NTOK * DMODEL];        // tf32-rounded u
__device__ float g_wa[(size_t)DPROJ * DMODEL];       // tf32-rounded in_proj_w
__device__ float g_wo[(size_t)DMODEL * DINNER];      // tf32-rounded out_proj_w

// ================= helpers =================
__device__ __forceinline__ uint32_t smem_u32(const void* p) {
    uint32_t a;
    asm("{ .reg .u64 t; cvta.to.shared.u64 t, %1; cvt.u32.u64 %0, t; }" : "=r"(a) : "l"(p));
    return a;
}
__device__ __forceinline__ void cp_async16(uint32_t s, const void* g) {
    asm volatile("cp.async.cg.shared.global [%0], [%1], 16;" :: "r"(s), "l"(g) : "memory");
}
__device__ __forceinline__ void sts_zero16(uint32_t s) {
    asm volatile("st.shared.v4.b32 [%0], {%1,%1,%1,%1};" :: "r"(s), "r"(0u) : "memory");
}
#define CP_COMMIT() asm volatile("cp.async.commit_group;" ::: "memory")
#define CP_WAIT2()  asm volatile("cp.async.wait_group 2;" ::: "memory")

__device__ __forceinline__ float tf32_rn(float x) {
    uint32_t r;
    asm("cvt.rna.tf32.f32 %0, %1;" : "=r"(r) : "f"(x));
    return __uint_as_float(r);
}
__device__ __forceinline__ void mma_tf32(float& d0, float& d1, float& d2, float& d3,
                                         uint32_t a0, uint32_t a1, uint32_t a2, uint32_t a3,
                                         uint32_t b0, uint32_t b1) {
    asm volatile(
        "mma.sync.aligned.m16n8k8.row.col.f32.tf32.tf32.f32 "
        "{%0,%1,%2,%3}, {%4,%5,%6,%7}, {%8,%9}, {%0,%1,%2,%3};"
        : "+f"(d0), "+f"(d1), "+f"(d2), "+f"(d3)
        : "r"(a0), "r"(a1), "r"(a2), "r"(a3), "r"(b0), "r"(b1));
}

// ================= tf32 rounding pass =================
__global__ void tf32_round_kernel(const float* __restrict__ in, float* __restrict__ out, int n4) {
    int i = blockIdx.x * blockDim.x + threadIdx.x;
    if (i >= n4) return;
    float4 v = ((const float4*)in)[i];
    v.x = tf32_rn(v.x); v.y = tf32_rn(v.y); v.z = tf32_rn(v.z); v.w = tf32_rn(v.w);
    ((float4*)out)[i] = v;
}

// ================= TF32 mma.sync GEMM (NT): C[m,n] = sum_k A[m,k]B[n,k] =================
// Block 128x128, 256 thr (8 warps 2x4, warp tile 64x32), k-tile 16, 4-stage cp.async.
#define KTILE   16
#define TSTRIDE 20                              // floats per row in smem (16 + 4 pad)
#define TILE_FLOATS (128 * TSTRIDE)             // 2560 floats per operand tile
#define GSTAGE_FLOATS (2 * TILE_FLOATS)         // A + B
#define SMEM_GEMM (4 * GSTAGE_FLOATS * 4)       // 81920 bytes

__device__ __forceinline__ void load_tile_mma(const float* __restrict__ A,
                                              const float* __restrict__ B,
                                              int K, int Nn, int bm, int bn,
                                              int ti, uint32_t sb, int tid)
{
    uint32_t st = sb + (uint32_t)(ti & 3) * (GSTAGE_FLOATS * 4);
    const float* ag = A + (size_t)bm * K + (size_t)ti * KTILE;
#pragma unroll
    for (int i = 0; i < 2; i++) {                 // A: 128 rows x 4 chunks
        int flat = tid + (i << 8);
        int r = flat >> 2, c = flat & 3;
        cp_async16(st + r * (TSTRIDE * 4) + c * 16, ag + (size_t)r * K + c * 4);
    }
    uint32_t stb = st + TILE_FLOATS * 4;
    const float* bg = B + (size_t)ti * KTILE;
#pragma unroll
    for (int i = 0; i < 2; i++) {                 // B: 128 rows x 4 chunks
        int flat = tid + (i << 8);
        int r = flat >> 2, c = flat & 3;
        uint32_t so = stb + r * (TSTRIDE * 4) + c * 16;
        int gn = bn + r;
        if (gn < Nn) cp_async16(so, bg + (size_t)gn * K + c * 4);
        else         sts_zero16(so);
    }
}

__global__ void __launch_bounds__(256, 2)
gemm_mma(const float* __restrict__ A, const float* __restrict__ B,
         float* __restrict__ C, int M, int Nn, int K)
{
    extern __shared__ float dsm[];
    const int tid = threadIdx.x;
    const int wid = tid >> 5;
    const int lane = tid & 31;
    const int g = lane >> 2;                     // group id 0..7
    const int q = lane & 3;                      // thread in group
    const int wm = (wid & 1) * 64;               // warp M offset
    const int wn = (wid >> 1) * 32;              // warp N offset
    const int KT = K / KTILE;
    const int bm = blockIdx.y << 7;
    const int bn = blockIdx.x << 7;
    uint32_t sb = smem_u32(dsm);

    float acc[4][4][4];
#pragma unroll
    for (int mi = 0; mi < 4; mi++)
#pragma unroll
        for (int ni = 0; ni < 4; ni++)
#pragma unroll
            for (int e = 0; e < 4; e++) acc[mi][ni][e] = 0.f;

    // prologue: stages 0..2
#pragma unroll
    for (int t = 0; t < 3; t++) {
        load_tile_mma(A, B, K, Nn, bm, bn, t, sb, tid);
        CP_COMMIT();
    }

    for (int kt = 0; kt < KT; kt++) {
        CP_WAIT2();                 // stage kt resident
        __syncthreads();            // everyone done with stage kt-1 (slot being refilled)
        int ld = kt + 3;
        if (ld < KT) load_tile_mma(A, B, K, Nn, bm, bn, ld, sb, tid);
        CP_COMMIT();

        const float* As = dsm + (kt & 3) * GSTAGE_FLOATS;
        const float* Bs = As + TILE_FLOATS;
#pragma unroll
        for (int ks = 0; ks < 2; ks++) {
            int k0 = ks * 8;
            uint32_t a[4][4];
#pragma unroll
            for (int mi = 0; mi < 4; mi++) {
                int row = wm + mi * 16;
                a[mi][0] = __float_as_uint(As[(row + g)     * TSTRIDE + k0 + q]);
                a[mi][1] = __float_as_uint(As[(row + g + 8) * TSTRIDE + k0 + q]);
                a[mi][2] = __float_as_uint(As[(row + g)     * TSTRIDE + k0 + q + 4]);
                a[mi][3] = __float_as_uint(As[(row + g + 8) * TSTRIDE + k0 + q + 4]);
            }
            uint32_t b[4][2];
#pragma unroll
            for (int ni = 0; ni < 4; ni++) {
                int col = wn + ni * 8;
                b[ni][0] = __float_as_uint(Bs[(col + g) * TSTRIDE + k0 + q]);
                b[ni][1] = __float_as_uint(Bs[(col + g) * TSTRIDE + k0 + q + 4]);
            }
#pragma unroll
            for (int mi = 0; mi < 4; mi++)
#pragma unroll
                for (int ni = 0; ni < 4; ni++)
                    mma_tf32(acc[mi][ni][0], acc[mi][ni][1], acc[mi][ni][2], acc[mi][ni][3],
                             a[mi][0], a[mi][1], a[mi][2], a[mi][3],
                             b[ni][0], b[ni][1]);
        }
        __syncthreads();
    }

    // epilogue: direct register -> gmem (C layout row-major [M, Nn])
#pragma unroll
    for (int mi = 0; mi < 4; mi++) {
#pragma unroll
        for (int ni = 0; ni < 4; ni++) {
            int col = bn + wn + ni * 8 + 2 * q;
            if (col < Nn) {
                int r0 = bm + wm + mi * 16 + g;
                float2 v0 = make_float2(acc[mi][ni][0], acc[mi][ni][1]);
                float2 v1 = make_float2(acc[mi][ni][2], acc[mi][ni][3]);
                *(float2*)(C + (size_t)r0 * Nn + col) = v0;
                *(float2*)(C + (size_t)(r0 + 8) * Nn + col) = v1;
            }
        }
    }
}

// ================= conv + silu (register-rolling window, 16 t/thread) =================
__global__ void __launch_bounds__(256) conv_silu_kernel(const float* __restrict__ cw,
                                                        const float* __restrict__ cb)
{
    int ch = blockIdx.x * 256 + threadIdx.x;
    int tb = blockIdx.y * 16;
    int b = tb >> 12;
    int l0 = tb & (SEQLEN - 1);
    float c0 = cw[ch * 4 + 0], c1 = cw[ch * 4 + 1], c2 = cw[ch * 4 + 2], c3 = cw[ch * 4 + 3];
    float bias = cb[ch];
    const float* base = g_proj + (size_t)(b * SEQLEN) * DPROJ + ch;
    float* outb = g_xbc + (size_t)(b * SEQLEN) * DXBC + ch;
    float w0 = (l0 >= 3) ? base[(size_t)(l0 - 3) * DPROJ] : 0.f;
    float w1 = (l0 >= 2) ? base[(size_t)(l0 - 2) * DPROJ] : 0.f;
    float w2 = (l0 >= 1) ? base[(size_t)(l0 - 1) * DPROJ] : 0.f;
#pragma unroll
    for (int tt = 0; tt < 16; tt++) {
        float xv = base[(size_t)(l0 + tt) * DPROJ];
        float a = fmaf(c3, xv, fmaf(c2, w2, fmaf(c1, w1, fmaf(c0, w0, bias))));
        outb[(size_t)(l0 + tt) * DXBC] = a / (1.f + expf(-a));
        w0 = w1; w1 = w2; w2 = xv;
    }
}

// ================= dA cumsum: one warp per (b,h,c) =================
__global__ void __launch_bounds__(256) dacum_kernel()
{
    int gw = (blockIdx.x * blockDim.x + threadIdx.x) >> 5;
    int lane = threadIdx.x & 31;
    if (gw >= BATCH * NHEADS * NCHUNK) return;
    int c = gw & 31, h = (gw >> 5) & 31, b = gw >> 10;
    int t0 = b * SEQLEN + c * CHUNKSZ + lane * 4;
    float p[4], run = 0.f;
#pragma unroll
    for (int j = 0; j < 4; j++) {
        float v = g_proj[(size_t)(t0 + j) * DPROJ + (DXBC + DINNER) + h];
        run += fmaxf(v, 0.f) + log1pf(expf(-fabsf(v)));
        p[j] = run;
    }
    float tot = run;
#pragma unroll
    for (int off = 1; off < 32; off <<= 1) {
        float nb = __shfl_up_sync(0xFFFFFFFFu, tot, off);
        if (lane >= off) tot += nb;
    }
    float excl = tot - run;
    int ob = ((b * 32 + h) * 32 + c) * CHUNKSZ + lane * 4;
#pragma unroll
    for (int j = 0; j < 4; j++) g_dacum[ob + j] = -(excl + p[j]);
}

// ================= chunk states =================
#define SMEM_STATES ((2 * 128 * 65 + 128) * 4)
__global__ void __launch_bounds__(256, 1) states_kernel()
{
    extern __shared__ float sm[];
    float* Bs = sm;
    float* xs = sm + 128 * 65;
    float* da = xs + 128 * 65;

    int bi = blockIdx.x;
    int h = bi & 31, c = (bi >> 5) & 31, b = bi >> 10;
    int tid = threadIdx.x;
    int base_t = b * SEQLEN + c * CHUNKSZ;
    int dab = ((b * 32 + h) * 32 + c) * CHUNKSZ;

    if (tid < 128) da[tid] = g_dacum[dab + tid];
    __syncthreads();
    float da_last = da[127];

#pragma unroll
    for (int i = 0; i < 32; i++) {
        int flat = tid + 256 * i;
        int s = flat >> 6, p = flat & 63;
        size_t goff = (size_t)(base_t + s) * DXBC + h * 64 + p;
        float dec = __expf(da_last - da[s]);
        xs[s * 65 + p] = g_xbc[goff] * dec;
        Bs[s * 65 + p] = g_xbc[goff + DINNER];
    }
    __syncthreads();

    int n = tid & 63, pg = tid >> 6;
    float acc[16];
#pragma unroll
    for (int i = 0; i < 16; i++) acc[i] = 0.f;
    for (int s = 0; s < CHUNKSZ; s++) {
        float bv = Bs[s * 65 + n];
#pragma unroll
        for (int i = 0; i < 16; i++)
            acc[i] = fmaf(bv, xs[s * 65 + pg + 4 * i], acc[i]);
    }
    size_t sbo = (size_t)((b * 32 + c) * 32 + h) * (HDIM * DSTATE);
#pragma unroll
    for (int i = 0; i < 16; i++)
        g_states[sbo + (pg + 4 * i) * 64 + n] = acc[i];
}

// ================= inter-chunk scan =================
__global__ void __launch_bounds__(256) scan_kernel()
{
    int bi = blockIdx.x;               // (b*32+h)*16 + q
    int q = bi & 15;
    int bh = bi >> 4;
    int b = bh >> 5, h = bh & 31;
    int e = q * 256 + threadIdx.x;
    float carry = 0.f;
    for (int c = 0; c < NCHUNK; c++) {
        size_t sbo = (size_t)((b * 32 + c) * 32 + h) * (HDIM * DSTATE);
        float dec = expf(g_dacum[((b * 32 + h) * 32 + c) * CHUNKSZ + 127]);
        g_prev[sbo + e] = carry;
        carry = fmaf(carry, dec, g_states[sbo + e]);
    }
}

// ================= fused Y kernel =================
#define SMEM_Y ((3 * 128 * 65 + 128 * 129 + 64 * 65 + 128) * 4)
__global__ void __launch_bounds__(256, 1) y_kernel(const float* __restrict__ zb,
                                                   const float* __restrict__ Dp)
{
    extern __shared__ float sm[];
    float* Cs = sm;
    float* Bs = Cs + 128 * 65;
    float* xs = Bs + 128 * 65;
    float* G  = xs + 128 * 65;
    float* pT = G + 128 * 129;
    float* da = pT + 64 * 65;

    int bi = blockIdx.x;
    int h = bi & 31, c = (bi >> 5) & 31, b = bi >> 10;
    int tid = threadIdx.x;
    int base_t = b * SEQLEN + c * CHUNKSZ;
    int dab = ((b * 32 + h) * 32 + c) * CHUNKSZ;
    size_t pb = (size_t)((b * 32 + c) * 32 + h) * (HDIM * DSTATE);

    if (tid < 128) da[tid] = g_dacum[dab + tid];
#pragma unroll
    for (int i = 0; i < 32; i++) {
        int flat = tid + 256 * i;
        int s = flat >> 6, p = flat & 63;
        size_t goff = (size_t)(base_t + s) * DXBC + h * 64 + p;
        xs[s * 65 + p] = g_xbc[goff];
        Bs[s * 65 + p] = g_xbc[goff + DINNER];
        Cs[s * 65 + p] = g_xbc[goff + 2 * DINNER];
    }
#pragma unroll
    for (int i = 0; i < 16; i++) {
        int flat = tid + 256 * i;
        int p = flat >> 6, n = flat & 63;
        pT[n * 65 + p] = g_prev[pb + flat];
    }
    __syncthreads();

    {
        int tr = tid >> 4, tc = tid & 15;
        float accg[8][8];
#pragma unroll
        for (int i = 0; i < 8; i++)
#pragma unroll
            for (int j = 0; j < 8; j++) accg[i][j] = 0.f;
        for (int n = 0; n < DSTATE; n++) {
            float a[8], bb[8];
#pragma unroll
            for (int i = 0; i < 8; i++) a[i] = Cs[(tr + 16 * i) * 65 + n];
#pragma unroll
            for (int j = 0; j < 8; j++) bb[j] = Bs[(tc + 16 * j) * 65 + n];
#pragma unroll
            for (int i = 0; i < 8; i++)
#pragma unroll
                for (int j = 0; j < 8; j++)
                    accg[i][j] = fmaf(a[i], bb[j], accg[i][j]);
        }
#pragma unroll
        for (int i = 0; i < 8; i++) {
            int l = tr + 16 * i;
            float dal = da[l];
#pragma unroll
            for (int j = 0; j < 8; j++) {
                int s = tc + 16 * j;
                G[l * 129 + s] = (s <= l) ? accg[i][j] * __expf(dal - da[s]) : 0.f;
            }
        }
    }
    __syncthreads();

    {
        int p = tid & 63;
        int tr2 = tid >> 6;
        float acc[32], acc2[32];
#pragma unroll
        for (int i = 0; i < 32; i++) { acc[i] = 0.f; acc2[i] = 0.f; }

        for (int s = 0; s < CHUNKSZ; s++) {
            float xv = xs[s * 65 + p];
#pragma unroll
            for (int i = 0; i < 32; i++)
                acc[i] = fmaf(G[(tr2 + 4 * i) * 129 + s], xv, acc[i]);
        }
        for (int n = 0; n < DSTATE; n++) {
            float pv = pT[n * 65 + p];
#pragma unroll
            for (int i = 0; i < 32; i++)
                acc2[i] = fmaf(Cs[(tr2 + 4 * i) * 65 + n], pv, acc2[i]);
        }

        float Dh = Dp[h];
        int chn = h * 64 + p;
        float zbias = zb[chn];
#pragma unroll
        for (int i = 0; i < 32; i++) {
            int l = tr2 + 4 * i;
            int t = base_t + l;
            float yv = acc[i] + __expf(da[l]) * acc2[i] + Dh * xs[l * 65 + p];
            float zv = g_proj[(size_t)t * DPROJ + DXBC + chn] + zbias;
            float sil = zv / (1.f + expf(-zv));
            g_yz[(size_t)t * DINNER + chn] = tf32_rn(yv * sil);
        }
    }
}

// ================= launch =================
extern "C" void kernel_launch(void* const* d_in, const int* in_sizes, int n_in,
                              void* d_out, int out_size)
{
    const float* u          = (const float*)d_in[0];
    const float* in_proj_w  = (const float*)d_in[1];
    const float* z_bias     = (const float*)d_in[2];
    const float* conv_w     = (const float*)d_in[3];
    const float* conv_b     = (const float*)d_in[4];
    const float* Dparam     = (const float*)d_in[5];
    const float* out_proj_w = (const float*)d_in[6];
    float* out = (float*)d_out;

    void *p_proj = nullptr, *p_yz = nullptr, *p_ua = nullptr, *p_wa = nullptr, *p_wo = nullptr;
    cudaGetSymbolAddress(&p_proj, g_proj);
    cudaGetSymbolAddress(&p_yz, g_yz);
    cudaGetSymbolAddress(&p_ua, g_ua);
    cudaGetSymbolAddress(&p_wa, g_wa);
    cudaGetSymbolAddress(&p_wo, g_wo);

    cudaFuncSetAttribute(gemm_mma, cudaFuncAttributeMaxDynamicSharedMemorySize, SMEM_GEMM);
    cudaFuncSetAttribute(states_kernel, cudaFuncAttributeMaxDynamicSharedMemorySize, SMEM_STATES);
    cudaFuncSetAttribute(y_kernel, cudaFuncAttributeMaxDynamicSharedMemorySize, SMEM_Y);

    // 0) tf32-round operands (RN, halves truncation bias)
    tf32_round_kernel<<<(NTOK * DMODEL / 4 + 255) / 256, 256>>>(u, (float*)p_ua, NTOK * DMODEL / 4);
    tf32_round_kernel<<<(DPROJ * DMODEL / 4 + 255) / 256, 256>>>(in_proj_w, (float*)p_wa, DPROJ * DMODEL / 4);
    tf32_round_kernel<<<(DMODEL * DINNER / 4 + 255) / 256, 256>>>(out_proj_w, (float*)p_wo, DMODEL * DINNER / 4);

    // 1) in_proj GEMM (tf32 mma.sync): [8192,1024] x [8224,1024]^T
    {
        dim3 grid((DPROJ + 127) / 128, NTOK / 128);
        gemm_mma<<<grid, 256, SMEM_GEMM>>>((const float*)p_ua, (const float*)p_wa,
                                           (float*)p_proj, NTOK, DPROJ, DMODEL);
    }
    // 2) conv + silu
    {
        dim3 grid(DXBC / 256, NTOK / 16);
        conv_silu_kernel<<<grid, 256>>>(conv_w, conv_b);
    }
    // 3) dA cumsum
    dacum_kernel<<<(BATCH * NHEADS * NCHUNK * 32 + 255) / 256, 256>>>();
    // 4) chunk states
    states_kernel<<<BATCH * NCHUNK * NHEADS, 256, SMEM_STATES>>>();
    // 5) inter-chunk scan
    scan_kernel<<<BATCH * NHEADS * 16, 256>>>();
    // 6) fused Y + gating
    y_kernel<<<BATCH * NCHUNK * NHEADS, 256, SMEM_Y>>>(z_bias, Dparam);
    // 7) out_proj GEMM (tf32 mma.sync): [8192,2048] x [1024,2048]^T
    {
        dim3 grid(DMODEL / 128, NTOK / 128);
        gemm_mma<<<grid, 256, SMEM_GEMM>>>((const float*)p_yz, (const float*)p_wo,
                                           out, NTOK, DMODEL, DINNER);
    }
}